// round 6
// baseline (speedup 1.0000x reference)
#include <cuda_runtime.h>

// Shapes fixed by dataset: b=8, n=1024, m=2048, x_dim=1, c=3, Z=128
#define BB     8
#define NN     1024
#define MM     2048
#define MT     32          // m-rows per block in main kernel
#define NCTR   12          // Hermite centers, c_l = l - 5.5, spacing 1, r = 0.5
#define KH     13          // Hermite terms k = 0..12
#define EPSV   1e-8f
#define LOG2E  1.4426950408889634f
#define K2     (-0.5f * LOG2E)   // exp(-u^2/2) = exp2(K2*u^2)

// Scratch: moments M[b][ctr][k][ch], flat (b*12+ctr)*39 + k*3 + ch
__device__ float g_moments[BB * NCTR * KH * 3];

__device__ __forceinline__ float ex2f(float v) {
    float r;
    asm("ex2.approx.ftz.f32 %0, %1;" : "=f"(r) : "f"(v));
    return r;
}

// ---------------------------------------------------------------------------
// Kernel 1: per-(batch,center) moments  M_k,c = sum_{n in bucket} (x'-c)^k/k! * feat_c
// grid = 8*12 blocks, 128 threads
// ---------------------------------------------------------------------------
__global__ __launch_bounds__(128)
void moments_kernel(const float* __restrict__ x,
                    const float* __restrict__ y,
                    const float* __restrict__ sigma)
{
    __shared__ float msum[KH * 3];

    const int tid = threadIdx.x;
    const int b   = blockIdx.x / NCTR;
    const int ctr = blockIdx.x % NCTR;
    const float c = (float)ctr - 5.5f;

    const float s_inv = __expf(-sigma[0]);   // 1/scale

    if (tid < KH * 3) msum[tid] = 0.f;
    __syncthreads();

    // inverse factorials step: p_k = p_{k-1} * w / k
    const float INVK[KH] = {0.f, 1.f, 0.5f, 1.f/3.f, 0.25f, 0.2f, 1.f/6.f,
                            1.f/7.f, 0.125f, 1.f/9.f, 0.1f, 1.f/11.f, 1.f/12.f};

    float a0[KH], a1[KH], a2[KH];
    #pragma unroll
    for (int k = 0; k < KH; ++k) { a0[k] = 0.f; a1[k] = 0.f; a2[k] = 0.f; }

    const float*  xb = x + b * NN;
    const float2* yb = reinterpret_cast<const float2*>(y + b * NN * 2);

    for (int i = tid; i < NN; i += 128) {
        float  xv = xb[i] * s_inv;
        int l = (int)floorf(xv + 6.0f);
        l = min(max(l, 0), NCTR - 1);
        if (l == ctr) {
            float2 yv = yb[i];
            float w = xv - c;
            float p = 1.f;
            a0[0] += 1.f; a1[0] += yv.x; a2[0] += yv.y;
            #pragma unroll
            for (int k = 1; k < KH; ++k) {
                p = p * w * INVK[k];
                a0[k] += p;
                a1[k] = fmaf(p, yv.x, a1[k]);
                a2[k] = fmaf(p, yv.y, a2[k]);
            }
        }
    }
    __syncthreads();

    #pragma unroll
    for (int k = 0; k < KH; ++k) {
        atomicAdd(&msum[k * 3 + 0], a0[k]);
        atomicAdd(&msum[k * 3 + 1], a1[k]);
        atomicAdd(&msum[k * 3 + 2], a2[k]);
    }
    __syncthreads();

    if (tid < KH * 3)
        g_moments[(b * NCTR + ctr) * (KH * 3) + tid] = msum[tid];
}

// ---------------------------------------------------------------------------
// Kernel 2: per m-row evaluate Hermite series, normalize, project.
// grid = 8 * (2048/32) = 512 blocks, 128 threads (4 warps).
// Fast path: warp w handles centers w*3..w*3+2 for all 32 rows (lane = row).
// ---------------------------------------------------------------------------
__global__ __launch_bounds__(128)
void main_kernel(const float* __restrict__ x,
                 const float* __restrict__ y,
                 const float* __restrict__ t,
                 const float* __restrict__ sigma,
                 const float* __restrict__ W,
                 const float* __restrict__ bfc,
                 float* __restrict__ out)
{
    __shared__ float  sM[NCTR * KH * 3];   // moments for this batch
    __shared__ float4 red[4][MT];          // per-warp partials
    __shared__ float4 zfin[MT];            // (density, zn1, zn2, -)

    const int tid  = threadIdx.x;
    const int lane = tid & 31;
    const int wrp  = tid >> 5;
    const int blk  = blockIdx.x;
    const int b    = blk >> 6;              // 64 m-tiles per batch
    const int m_base = (blk & 63) * MT;

    const float C0 = -0.5f * LOG2E * __expf(-2.f * sigma[0]);
    const float C1 = -0.5f * LOG2E * __expf(-2.f * sigma[1]);
    const float C2 = -0.5f * LOG2E * __expf(-2.f * sigma[2]);
    const float s  = __expf(sigma[0]);
    const bool fast = (C0 == C1) && (C0 == C2) && (s >= 0.8f) && (s <= 1.25f);

    float s0 = 0.f, s1 = 0.f, s2 = 0.f;

    if (fast) {
        // load this batch's moments (468 floats)
        for (int i = tid; i < NCTR * KH * 3; i += 128)
            sM[i] = g_moments[b * (NCTR * KH * 3) + i];
        __syncthreads();

        const float tr = __ldg(t + b * MM + m_base + lane) / s;   // scaled t, lane = row

        #pragma unroll
        for (int cc = 0; cc < 3; ++cc) {
            const int   ctr = wrp * 3 + cc;
            const float c   = (float)ctr - 5.5f;
            const float u   = tr - c;
            const float E   = ex2f(K2 * u * u);
            const float* Mc = sM + ctr * (KH * 3);

            float Hk2 = E;                       // H_0
            s0 = fmaf(Mc[0], Hk2, s0);
            s1 = fmaf(Mc[1], Hk2, s1);
            s2 = fmaf(Mc[2], Hk2, s2);
            float Hk1 = u * E;                   // H_1
            s0 = fmaf(Mc[3], Hk1, s0);
            s1 = fmaf(Mc[4], Hk1, s1);
            s2 = fmaf(Mc[5], Hk1, s2);
            #pragma unroll
            for (int k = 2; k < KH; ++k) {
                float Hk = fmaf(u, Hk1, -(float)(k - 1) * Hk2);   // He recurrence * E
                const float* Mk = Mc + k * 3;
                s0 = fmaf(Mk[0], Hk, s0);
                s1 = fmaf(Mk[1], Hk, s1);
                s2 = fmaf(Mk[2], Hk, s2);
                Hk2 = Hk1; Hk1 = Hk;
            }
        }
    } else {
        // Exact direct fallback: thread (row=lane, quarter=wrp) scans 256 n's
        const float tr = __ldg(t + b * MM + m_base + lane);
        const float*  xb = x + b * NN + wrp * (NN / 4);
        const float2* yb = reinterpret_cast<const float2*>(y + b * NN * 2) + wrp * (NN / 4);
        for (int i = 0; i < NN / 4; ++i) {
            float  d  = tr - __ldg(xb + i);
            float2 yv = __ldg(yb + i);
            float d2 = d * d;
            float e0 = ex2f(C0 * d2);
            float e1 = ex2f(C1 * d2);
            float e2 = ex2f(C2 * d2);
            s0 += e0;
            s1 = fmaf(e1, yv.x, s1);
            s2 = fmaf(e2, yv.y, s2);
        }
        __syncthreads();   // match fast-path sync count before red[] use
    }

    red[wrp][lane] = make_float4(s0, s1, s2, 0.f);

    // W + bias into registers (column group k4 = lane) — verified mapping from R5
    const int k4 = lane;
    const float4* Wv = reinterpret_cast<const float4*>(W);
    const float4 wa  = __ldg(Wv + 3 * k4);
    const float4 wb  = __ldg(Wv + 3 * k4 + 1);
    const float4 wc  = __ldg(Wv + 3 * k4 + 2);
    const float4 bbv = __ldg(reinterpret_cast<const float4*>(bfc) + k4);

    __syncthreads();

    if (tid < MT) {
        float4 p0 = red[0][tid], p1 = red[1][tid], p2 = red[2][tid], p3 = red[3][tid];
        float d0 = p0.x + p1.x + p2.x + p3.x;
        float d1 = p0.y + p1.y + p2.y + p3.y;
        float d2 = p0.z + p1.z + p2.z + p3.z;
        float inv = 1.f / (d0 + EPSV);
        zfin[tid] = make_float4(d0, d1 * inv, d2 * inv, 0.f);
    }
    __syncthreads();

    // Epilogue: out[b, m_base+mi, 4*k4..4*k4+3]
    float4* out4 = reinterpret_cast<float4*>(out);
    const size_t rowbase = (size_t)(b * MM + m_base);
    #pragma unroll
    for (int mi = wrp; mi < MT; mi += 4) {
        float4 z = zfin[mi];
        float4 o;
        o.x = fmaf(z.x, wa.x, fmaf(z.y, wa.y, fmaf(z.z, wa.z, bbv.x)));
        o.y = fmaf(z.x, wa.w, fmaf(z.y, wb.x, fmaf(z.z, wb.y, bbv.y)));
        o.z = fmaf(z.x, wb.z, fmaf(z.y, wb.w, fmaf(z.z, wc.x, bbv.z)));
        o.w = fmaf(z.x, wc.y, fmaf(z.y, wc.z, fmaf(z.z, wc.w, bbv.w)));
        out4[(rowbase + mi) * 32 + k4] = o;
    }
}

extern "C" void kernel_launch(void* const* d_in, const int* in_sizes, int n_in,
                              void* d_out, int out_size)
{
    const float* x     = (const float*)d_in[0];   // (8,1024,1)
    const float* y     = (const float*)d_in[1];   // (8,1024,2)
    const float* t     = (const float*)d_in[2];   // (8,2048,1)
    const float* sigma = (const float*)d_in[3];   // (3,)
    const float* W     = (const float*)d_in[4];   // (128,3)
    const float* bfc   = (const float*)d_in[5];   // (128,)
    float* out = (float*)d_out;                   // (8,2048,128)

    moments_kernel<<<BB * NCTR, 128>>>(x, y, sigma);
    main_kernel<<<BB * (MM / MT), 128>>>(x, y, t, sigma, W, bfc, out);
}

// round 7
// speedup vs baseline: 8.8796x; 8.8796x over previous
#include <cuda_runtime.h>

// Shapes fixed by dataset: b=8, n=1024, m=2048, x_dim=1, c=3, Z=128
#define BB     8
#define NN     1024
#define MM     2048
#define MT     32          // m-rows per block in main kernel
#define NCTR   12          // Hermite centers, c_l = l - 5.5, spacing 1, r = 0.5
#define KH     13          // Hermite terms k = 0..12
#define EPSV   1e-8f
#define LOG2E  1.4426950408889634f
#define K2     (-0.5f * LOG2E)   // exp(-u^2/2) = exp2(K2*u^2)

// Scratch: moments M[b][ctr][k][ch], flat (b*12+ctr)*39 + k*3 + ch
__device__ float g_moments[BB * NCTR * KH * 3];

__device__ __forceinline__ float ex2f(float v) {
    float r;
    asm("ex2.approx.ftz.f32 %0, %1;" : "=f"(r) : "f"(v));
    return r;
}

// ---------------------------------------------------------------------------
// Kernel 1: moments M_k,c = sum_{n in bucket(ctr)} (x'-c)^k/k! * feat_ch
// One warp per (batch,center): 96 blocks x 32 threads. NO atomics:
// register accumulate -> shfl butterfly -> lane 0 stores.
// ---------------------------------------------------------------------------
__global__ __launch_bounds__(32)
void moments_kernel(const float* __restrict__ x,
                    const float* __restrict__ y,
                    const float* __restrict__ sigma)
{
    const int lane = threadIdx.x;
    const int b    = blockIdx.x / NCTR;
    const int ctr  = blockIdx.x % NCTR;
    const float c  = (float)ctr - 5.5f;

    const float s_inv = __expf(-sigma[0]);   // 1/scale

    const float INVK[KH] = {0.f, 1.f, 0.5f, 1.f/3.f, 0.25f, 0.2f, 1.f/6.f,
                            1.f/7.f, 0.125f, 1.f/9.f, 0.1f, 1.f/11.f, 1.f/12.f};

    float a0[KH], a1[KH], a2[KH];
    #pragma unroll
    for (int k = 0; k < KH; ++k) { a0[k] = 0.f; a1[k] = 0.f; a2[k] = 0.f; }

    const float*  xb = x + b * NN;
    const float2* yb = reinterpret_cast<const float2*>(y + b * NN * 2);

    for (int i = lane; i < NN; i += 32) {
        float xv = __ldg(xb + i) * s_inv;
        int l = (int)floorf(xv + 6.0f);
        l = min(max(l, 0), NCTR - 1);
        if (l == ctr) {
            float2 yv = __ldg(yb + i);
            float w = xv - c;
            float p = 1.f;
            a0[0] += 1.f; a1[0] += yv.x; a2[0] += yv.y;
            #pragma unroll
            for (int k = 1; k < KH; ++k) {
                p = p * w * INVK[k];
                a0[k] += p;
                a1[k] = fmaf(p, yv.x, a1[k]);
                a2[k] = fmaf(p, yv.y, a2[k]);
            }
        }
    }

    // Warp butterfly reduction of all 39 accumulators
    #pragma unroll
    for (int off = 16; off; off >>= 1) {
        #pragma unroll
        for (int k = 0; k < KH; ++k) {
            a0[k] += __shfl_xor_sync(0xffffffffu, a0[k], off);
            a1[k] += __shfl_xor_sync(0xffffffffu, a1[k], off);
            a2[k] += __shfl_xor_sync(0xffffffffu, a2[k], off);
        }
    }

    if (lane == 0) {
        float* dst = g_moments + (b * NCTR + ctr) * (KH * 3);
        #pragma unroll
        for (int k = 0; k < KH; ++k) {
            dst[k * 3 + 0] = a0[k];
            dst[k * 3 + 1] = a1[k];
            dst[k * 3 + 2] = a2[k];
        }
    }
}

// ---------------------------------------------------------------------------
// Kernel 2: evaluate Hermite series per m-row, normalize, project.
// 512 blocks x 384 threads (12 warps). Warp = one center, lane = one of 32 rows.
// ---------------------------------------------------------------------------
__global__ __launch_bounds__(384)
void main_kernel(const float* __restrict__ x,
                 const float* __restrict__ y,
                 const float* __restrict__ t,
                 const float* __restrict__ sigma,
                 const float* __restrict__ W,
                 const float* __restrict__ bfc,
                 float* __restrict__ out)
{
    __shared__ float4 red[NCTR][MT];   // per-warp partials (6 KB)
    __shared__ float4 zfin[MT];        // (density, zn1, zn2, -)

    const int tid  = threadIdx.x;
    const int lane = tid & 31;         // row within tile
    const int wrp  = tid >> 5;         // 0..11 = center (fast) / n-slice (fallback)
    const int blk  = blockIdx.x;
    const int b    = blk >> 6;         // 64 m-tiles per batch
    const int m_base = (blk & 63) * MT;

    const float C0 = -0.5f * LOG2E * __expf(-2.f * sigma[0]);
    const float C1 = -0.5f * LOG2E * __expf(-2.f * sigma[1]);
    const float C2 = -0.5f * LOG2E * __expf(-2.f * sigma[2]);
    const float s  = __expf(sigma[0]);
    const bool fast = (C0 == C1) && (C0 == C2) && (s >= 0.8f) && (s <= 1.25f);

    float s0 = 0.f, s1 = 0.f, s2 = 0.f;

    if (fast) {
        const float tr = __ldg(t + b * MM + m_base + lane) / s;  // scaled t
        const float c  = (float)wrp - 5.5f;
        const float u  = tr - c;
        const float E  = ex2f(K2 * u * u);
        const float* Mc = g_moments + (b * NCTR + wrp) * (KH * 3);  // warp-uniform

        float Hk2 = E;                        // He_0 * E
        s0 = fmaf(__ldg(Mc + 0), Hk2, s0);
        s1 = fmaf(__ldg(Mc + 1), Hk2, s1);
        s2 = fmaf(__ldg(Mc + 2), Hk2, s2);
        float Hk1 = u * E;                    // He_1 * E
        s0 = fmaf(__ldg(Mc + 3), Hk1, s0);
        s1 = fmaf(__ldg(Mc + 4), Hk1, s1);
        s2 = fmaf(__ldg(Mc + 5), Hk1, s2);
        #pragma unroll
        for (int k = 2; k < KH; ++k) {
            float Hk = fmaf(u, Hk1, -(float)(k - 1) * Hk2);   // He recurrence * E
            const float* Mk = Mc + k * 3;
            s0 = fmaf(__ldg(Mk + 0), Hk, s0);
            s1 = fmaf(__ldg(Mk + 1), Hk, s1);
            s2 = fmaf(__ldg(Mk + 2), Hk, s2);
            Hk2 = Hk1; Hk1 = Hk;
        }
    } else {
        // Exact direct fallback: warp wrp scans its n-slice for all 32 rows
        const float tr = __ldg(t + b * MM + m_base + lane);
        const int nstart = wrp * 86;
        const int nend   = min(NN, nstart + 86);
        const float*  xb = x + b * NN;
        const float2* yb = reinterpret_cast<const float2*>(y + b * NN * 2);
        for (int i = nstart; i < nend; ++i) {
            float  d  = tr - __ldg(xb + i);
            float2 yv = __ldg(yb + i);
            float d2 = d * d;
            float e0 = ex2f(C0 * d2);
            float e1 = ex2f(C1 * d2);
            float e2 = ex2f(C2 * d2);
            s0 += e0;
            s1 = fmaf(e1, yv.x, s1);
            s2 = fmaf(e2, yv.y, s2);
        }
    }

    red[wrp][lane] = make_float4(s0, s1, s2, 0.f);

    // W + bias into registers (column group k4 = lane)
    const int k4 = lane;
    const float4* Wv = reinterpret_cast<const float4*>(W);
    const float4 wa  = __ldg(Wv + 3 * k4);
    const float4 wb  = __ldg(Wv + 3 * k4 + 1);
    const float4 wc  = __ldg(Wv + 3 * k4 + 2);
    const float4 bbv = __ldg(reinterpret_cast<const float4*>(bfc) + k4);

    __syncthreads();

    // Warp 0: combine 12 center/slice partials per row, normalize
    if (tid < MT) {
        float d0 = 0.f, d1 = 0.f, d2 = 0.f;
        #pragma unroll
        for (int wdx = 0; wdx < NCTR; ++wdx) {
            float4 p = red[wdx][tid];
            d0 += p.x; d1 += p.y; d2 += p.z;
        }
        float inv = 1.f / (d0 + EPSV);
        zfin[tid] = make_float4(d0, d1 * inv, d2 * inv, 0.f);
    }
    __syncthreads();

    // Epilogue: out[b, m_base+mi, 4*k4..4*k4+3], coalesced float4 stores
    float4* out4 = reinterpret_cast<float4*>(out);
    const size_t rowbase = (size_t)(b * MM + m_base);
    for (int mi = wrp; mi < MT; mi += NCTR) {
        float4 z = zfin[mi];      // warp-uniform broadcast LDS
        float4 o;
        o.x = fmaf(z.x, wa.x, fmaf(z.y, wa.y, fmaf(z.z, wa.z, bbv.x)));
        o.y = fmaf(z.x, wa.w, fmaf(z.y, wb.x, fmaf(z.z, wb.y, bbv.y)));
        o.z = fmaf(z.x, wb.z, fmaf(z.y, wb.w, fmaf(z.z, wc.x, bbv.z)));
        o.w = fmaf(z.x, wc.y, fmaf(z.y, wc.z, fmaf(z.z, wc.w, bbv.w)));
        out4[(rowbase + mi) * 32 + k4] = o;
    }
}

extern "C" void kernel_launch(void* const* d_in, const int* in_sizes, int n_in,
                              void* d_out, int out_size)
{
    const float* x     = (const float*)d_in[0];   // (8,1024,1)
    const float* y     = (const float*)d_in[1];   // (8,1024,2)
    const float* t     = (const float*)d_in[2];   // (8,2048,1)
    const float* sigma = (const float*)d_in[3];   // (3,)
    const float* W     = (const float*)d_in[4];   // (128,3)
    const float* bfc   = (const float*)d_in[5];   // (128,)
    float* out = (float*)d_out;                   // (8,2048,128)

    moments_kernel<<<BB * NCTR, 32>>>(x, y, sigma);
    main_kernel<<<BB * (MM / MT), 384>>>(x, y, t, sigma, W, bfc, out);
}